// round 15
// baseline (speedup 1.0000x reference)
#include <cuda_runtime.h>
#include <cuda_fp16.h>
#include <stdint.h>
#include <math.h>

#define B_N  16384
#define D_N  2048
#define E_N  10
#define H1_N 512
#define H2_N 64
#define TMS  128
#define KC   64
#define NCHUNKS (D_N / KC)          /* 32 */
#define MAX_TILES (B_N / TMS + E_N) /* 138 */
#define NTHREADS 512

/* ---- smem byte offsets ---- */
#define SO_RIDX 0          /* 128 int */
#define SO_B1   512        /* 512 f   */
#define SO_B2   2560       /* 64 f    */
#define SO_W3   2816       /* 128 f   */
#define SO_B3   3328       /* 2 f     */
#define SO_A    4096       /* 2 x 18432 (A tiles [128][72] fp16) -> ends 40960 */
#define SO_BB   40960      /* 2 x 36864 (B tiles [256][72] fp16) -> ends 114688 */
#define SO_C2   114688     /* c2 park: 512 thr x 16 f = 32768 -> ends 147456 */
#define SO_H1   4096       /* OVERLAY: h1 [128][264] fp16 = 67584 (bufs dead)  */
#define SMEM_TOT 147456    /* 1 CTA/SM, 512 threads, 16 warps */

/* ---------------- device globals ---------------- */
__device__ __align__(16) __half g_W1T[(size_t)E_N * H1_N * D_N]; /* [e][n(512)][k(2048)] */
__device__ __align__(16) __half g_W2T[H2_N * H1_N];              /* [n(64)][k(512)]      */
__device__ int g_cnt[E_N];          /* zero-init; reset by tile-builder each run */
__device__ int g_done;              /* zero-init; reset by tile-builder each run */
__device__ int g_cur[E_N];
__device__ int g_sorted[B_N];
__device__ int g_te[MAX_TILES], g_ts[MAX_TILES], g_tr[MAX_TILES];
__device__ int g_ntile;

/* ---------------- helpers ---------------- */
__device__ __forceinline__ uint32_t smem_u32(const void* p) {
    uint32_t a;
    asm("{ .reg .u64 t; cvta.to.shared.u64 t, %1; cvt.u32.u64 %0, t; }" : "=r"(a) : "l"(p));
    return a;
}

#define LDM4(r, addr) asm volatile( \
    "ldmatrix.sync.aligned.m8n8.x4.shared.b16 {%0,%1,%2,%3}, [%4];" \
    : "=r"((r)[0]), "=r"((r)[1]), "=r"((r)[2]), "=r"((r)[3]) : "r"(addr))

/* fp32-accumulate MMA (layer 2) */
#define MMA(c, a, b0, b1) asm volatile( \
    "mma.sync.aligned.m16n8k16.row.col.f32.f16.f16.f32 " \
    "{%0,%1,%2,%3},{%4,%5,%6,%7},{%8,%9},{%0,%1,%2,%3};" \
    : "+f"((c)[0]), "+f"((c)[1]), "+f"((c)[2]), "+f"((c)[3]) \
    : "r"((a)[0]), "r"((a)[1]), "r"((a)[2]), "r"((a)[3]), "r"(b0), "r"(b1))

/* fp16-accumulate MMA (layer 1 mainloop, split accumulation) */
#define MMA16(c, a, b0, b1) asm volatile( \
    "mma.sync.aligned.m16n8k16.row.col.f16.f16.f16.f16 " \
    "{%0,%1},{%2,%3,%4,%5},{%6,%7},{%0,%1};" \
    : "+r"((c)[0]), "+r"((c)[1]) \
    : "r"((a)[0]), "r"((a)[1]), "r"((a)[2]), "r"((a)[3]), "r"(b0), "r"(b1))

#define CP_ASYNC16(dst, src) asm volatile( \
    "cp.async.cg.shared.global [%0], [%1], 16;" :: "r"(dst), "l"(src))
#define CP_COMMIT() asm volatile("cp.async.commit_group;" ::: "memory")
#define CP_WAIT0()  asm volatile("cp.async.wait_group 0;" ::: "memory")

/* ------- bake W1 + W2 in one kernel (z==E_N branch does W2) ------- */
__global__ void bake_all(const float* __restrict__ W1, const float* __restrict__ W2) {
    __shared__ float t[64][65];
    const int tid = threadIdx.x;
    if (blockIdx.z == E_N) {
        if (blockIdx.x >= 16 || blockIdx.y >= 2) return;
        const int kb = blockIdx.x, nbb = blockIdx.y;
#pragma unroll
        for (int i = 0; i < 4; i++) {
            int idx = tid + i * 256, r = idx >> 5, c = idx & 31;
            t[r][c] = W2[(kb * 32 + r) * H2_N + nbb * 32 + c];
        }
        __syncthreads();
#pragma unroll
        for (int i = 0; i < 4; i++) {
            int idx = tid + i * 256, n = idx >> 5, k = idx & 31;
            g_W2T[(nbb * 32 + n) * H1_N + kb * 32 + k] = __float2half_rn(t[k][n]);
        }
        return;
    }
    const int kb = blockIdx.x, hb = blockIdx.y, e = blockIdx.z;
    const float* src = W1 + ((size_t)e * D_N + kb * 64) * H1_N + hb * 64;
#pragma unroll
    for (int i = 0; i < 4; i++) {
        int idx = tid + i * 256;
        int r = idx >> 4, c4 = idx & 15;
        float4 v = *(const float4*)(src + (size_t)r * H1_N + c4 * 4);
        t[r][c4 * 4 + 0] = v.x; t[r][c4 * 4 + 1] = v.y;
        t[r][c4 * 4 + 2] = v.z; t[r][c4 * 4 + 3] = v.w;
    }
    __syncthreads();
#pragma unroll
    for (int i = 0; i < 2; i++) {
        int idx = tid + i * 256;
        int n = idx >> 3, kg = idx & 7, k0 = kg * 8;
        __half2 p[4];
#pragma unroll
        for (int j = 0; j < 4; j++)
            p[j] = __floats2half2_rn(t[k0 + 2 * j][n], t[k0 + 2 * j + 1][n]);
        uint4 u;
        u.x = *(uint32_t*)&p[0]; u.y = *(uint32_t*)&p[1];
        u.z = *(uint32_t*)&p[2]; u.w = *(uint32_t*)&p[3];
        *(uint4*)(g_W1T + ((size_t)e * H1_N + hb * 64 + n) * D_N + kb * 64 + k0) = u;
    }
}

/* ------- hist + tile table fused: last finished block builds the table ------- */
__global__ void route_hist_tiles(const int* __restrict__ y) {
    __shared__ int c[E_N];
    __shared__ int last;
    const int t = threadIdx.x;
    if (t < E_N) c[t] = 0;
    __syncthreads();
    for (int i = blockIdx.x * blockDim.x + t; i < B_N; i += gridDim.x * blockDim.x)
        atomicAdd(&c[y[i]], 1);
    __syncthreads();
    if (t < E_N && c[t]) atomicAdd(&g_cnt[t], c[t]);
    __threadfence();
    if (t == 0) last = (atomicAdd(&g_done, 1) == (int)gridDim.x - 1);
    __syncthreads();
    if (!last || t >= 32) return;
    int cn = (t < E_N) ? g_cnt[t] : 0;
    if (t < E_N) g_cnt[t] = 0;
    if (t == 0) g_done = 0;
    int v = cn;
#pragma unroll
    for (int d = 1; d < 32; d <<= 1) {
        int u = __shfl_up_sync(0xFFFFFFFFu, v, d);
        if (t >= d) v += u;
    }
    int off = v - cn;
    int ntl = (cn + TMS - 1) / TMS;
    int tv = ntl;
#pragma unroll
    for (int d = 1; d < 32; d <<= 1) {
        int u = __shfl_up_sync(0xFFFFFFFFu, tv, d);
        if (t >= d) tv += u;
    }
    int tbase = tv - ntl;
    if (t < E_N) {
        g_cur[t] = off;
        for (int s = 0, j = 0; s < cn; s += TMS, j++) {
            g_te[tbase + j] = t;
            g_ts[tbase + j] = off + s;
            g_tr[tbase + j] = (cn - s) < TMS ? (cn - s) : TMS;
        }
    }
    if (t == 31) g_ntile = tv;
}
__global__ void route_scatter(const int* __restrict__ y) {
    __shared__ int lcnt[E_N], lbase[E_N], lcur[E_N];
    const int t = threadIdx.x, i0 = blockIdx.x * 256;
    if (t < E_N) { lcnt[t] = 0; lcur[t] = 0; }
    __syncthreads();
    const int e = y[i0 + t];
    atomicAdd(&lcnt[e], 1);
    __syncthreads();
    if (t < E_N && lcnt[t]) lbase[t] = atomicAdd(&g_cur[t], lcnt[t]);
    __syncthreads();
    int off = atomicAdd(&lcur[e], 1);
    g_sorted[lbase[e] + off] = i0 + t;
}

/* ------- fused mma.sync kernel: M=128 tile, 512 threads, fp16-acc mainloop ------- */
__global__ void __launch_bounds__(NTHREADS, 1)
fused_mma(const float* __restrict__ x, const float* __restrict__ b1,
          const float* __restrict__ b2, const float* __restrict__ W3,
          const float* __restrict__ b3, float* __restrict__ out)
{
    const int bid = blockIdx.x;
    if (bid >= g_ntile) return;
    extern __shared__ char smem[];
    const uint32_t sbase = smem_u32(smem);
    const int tid = threadIdx.x, lane = tid & 31, wid = tid >> 5;
    const int gid = lane >> 2, tIG = lane & 3;
    const int wm = wid >> 2, wn = wid & 3;      /* 4M x 4N warp grid */
    const int mbase = wm * 32;
    const int e = g_te[bid], st = g_ts[bid], rows = g_tr[bid];

    int*   ridx = (int*)(smem + SO_RIDX);
    float* b1s  = (float*)(smem + SO_B1);
    float* b2s  = (float*)(smem + SO_B2);
    float* w3s  = (float*)(smem + SO_W3);
    float* b3s  = (float*)(smem + SO_B3);
    float* c2s  = (float*)(smem + SO_C2) + tid * 16;
    if (tid < 128) {
        int r = tid < rows ? tid : (rows - 1);
        ridx[tid] = g_sorted[st + r];
        ((float4*)b1s)[tid] = ((const float4*)(b1 + e * H1_N))[tid];
    }
    if (tid < 16) ((float4*)b2s)[tid] = ((const float4*)b2)[tid];
    if (tid < 32) ((float4*)w3s)[tid] = ((const float4*)W3)[tid];
    if (tid < 2)  b3s[tid] = b3[tid];
    __syncthreads();

    const __half* W1Te = g_W1T + (size_t)e * H1_N * D_N;

    for (int nb = 0; nb < 2; nb++) {
        float c1f[2][8][4];
#pragma unroll
        for (int a = 0; a < 2; a++)
#pragma unroll
            for (int b = 0; b < 8; b++)
#pragma unroll
                for (int q = 0; q < 4; q++) c1f[a][b][q] = 0.f;

        /* ---- prologue: chunk 0 -> buf 0 ---- */
#pragma unroll
        for (int i = 0; i < 4; i++) {
            int idx = tid + i * NTHREADS, row = idx >> 3, seg = idx & 7;
            uint32_t dst = sbase + SO_BB + (row * 72 + seg * 8) * 2;
            CP_ASYNC16(dst, W1Te + (size_t)(nb * 256 + row) * D_N + seg * 8);
        }
#pragma unroll
        for (int i = 0; i < 4; i++) {
            int idx = tid + i * NTHREADS, row = idx >> 4, f4 = idx & 15;
            float4 v = *((const float4*)(x + (size_t)ridx[row] * D_N) + f4);
            __half2 h0 = __floats2half2_rn(v.x, v.y);
            __half2 h1h = __floats2half2_rn(v.z, v.w);
            uint2 u; u.x = *(uint32_t*)&h0; u.y = *(uint32_t*)&h1h;
            *(uint2*)(smem + SO_A + (row * 72 + f4 * 4) * 2) = u;
        }
        CP_COMMIT();

        /* ---- mainloop ---- */
        for (int c = 0; c < NCHUNKS; c++) {
            const int buf = c & 1, nbuf = buf ^ 1;
            CP_WAIT0();
            __syncthreads();

            /* prefetch next: B via cp.async; A as RAW float4 held across MMA */
            float4 av[4];
            if (c + 1 < NCHUNKS) {
#pragma unroll
                for (int i = 0; i < 4; i++) {
                    int idx = tid + i * NTHREADS, row = idx >> 3, seg = idx & 7;
                    uint32_t dst = sbase + SO_BB + nbuf * 36864 + (row * 72 + seg * 8) * 2;
                    CP_ASYNC16(dst, W1Te + (size_t)(nb * 256 + row) * D_N + (c + 1) * KC + seg * 8);
                }
#pragma unroll
                for (int i = 0; i < 4; i++) {
                    int idx = tid + i * NTHREADS, row = idx >> 4, f4 = idx & 15;
                    av[i] = *((const float4*)(x + (size_t)ridx[row] * D_N + (c + 1) * KC) + f4);
                }
            }

            /* fp16 accumulators for this K=64 chunk only */
            uint32_t c1h[2][8][2];
#pragma unroll
            for (int a = 0; a < 2; a++)
#pragma unroll
                for (int b = 0; b < 8; b++) { c1h[a][b][0] = 0u; c1h[a][b][1] = 0u; }

            const uint32_t aB = sbase + SO_A + buf * 18432
                              + ((mbase + (lane & 15)) * 72 + (lane >> 4) * 8) * 2;
            const uint32_t bB = sbase + SO_BB + buf * 36864
                              + ((wn * 64 + (lane & 7) + ((lane >> 4) & 1) * 8) * 72
                                 + ((lane >> 3) & 1) * 8) * 2;
#pragma unroll
            for (int ks = 0; ks < 4; ks++) {
                uint32_t a0[4], a1[4];
                LDM4(a0, aB + ks * 32);
                LDM4(a1, aB + 2304 + ks * 32);   /* mt=1: 16*72*2 */
#pragma unroll
                for (int nt2 = 0; nt2 < 4; nt2++) {
                    uint32_t bb[4];
                    LDM4(bb, bB + nt2 * 2304 + ks * 32);
                    MMA16(c1h[0][nt2 * 2],     a0, bb[0], bb[1]);
                    MMA16(c1h[0][nt2 * 2 + 1], a0, bb[2], bb[3]);
                    MMA16(c1h[1][nt2 * 2],     a1, bb[0], bb[1]);
                    MMA16(c1h[1][nt2 * 2 + 1], a1, bb[2], bb[3]);
                }
            }

            if (c + 1 < NCHUNKS) {
#pragma unroll
                for (int i = 0; i < 4; i++) {
                    int idx = tid + i * NTHREADS, row = idx >> 4, f4 = idx & 15;
                    __half2 h0 = __floats2half2_rn(av[i].x, av[i].y);
                    __half2 h1h = __floats2half2_rn(av[i].z, av[i].w);
                    uint2 u; u.x = *(uint32_t*)&h0; u.y = *(uint32_t*)&h1h;
                    *(uint2*)(smem + SO_A + nbuf * 18432 + (row * 72 + f4 * 4) * 2) = u;
                }
                CP_COMMIT();
            }

            /* spill fp16 chunk accumulators into persistent fp32 */
#pragma unroll
            for (int a = 0; a < 2; a++)
#pragma unroll
            for (int b = 0; b < 8; b++) {
                float2 lo = __half22float2(*(__half2*)&c1h[a][b][0]);
                float2 hi = __half22float2(*(__half2*)&c1h[a][b][1]);
                c1f[a][b][0] += lo.x; c1f[a][b][1] += lo.y;
                c1f[a][b][2] += hi.x; c1f[a][b][3] += hi.y;
            }
        }
        __syncthreads();   /* overlay safety */

        /* ---- h1 = relu(c1f + b1) -> fp16 stage [128][264] (overlay) ---- */
        __half* h1s = (__half*)(smem + SO_H1);
#pragma unroll
        for (int mt = 0; mt < 2; mt++)
#pragma unroll
        for (int nt = 0; nt < 8; nt++) {
            int m0 = mbase + mt * 16 + gid;
            int cl = wn * 64 + nt * 8 + tIG * 2;
            int cg = nb * 256 + cl;
            __half2 lo = __floats2half2_rn(fmaxf(c1f[mt][nt][0] + b1s[cg],     0.f),
                                           fmaxf(c1f[mt][nt][1] + b1s[cg + 1], 0.f));
            __half2 hi = __floats2half2_rn(fmaxf(c1f[mt][nt][2] + b1s[cg],     0.f),
                                           fmaxf(c1f[mt][nt][3] + b1s[cg + 1], 0.f));
            *(__half2*)(h1s + m0 * 264 + cl)       = lo;
            *(__half2*)(h1s + (m0 + 8) * 264 + cl) = hi;
        }
        __syncthreads();

        /* ---- layer2 partial GEMM (K = this pass's 256 cols); W2 from L2 ----
           c2 lives in regs ONLY inside this section; parked in smem between passes */
        {
            float c2[2][2][4];
            if (nb == 0) {
#pragma unroll
                for (int a = 0; a < 2; a++)
#pragma unroll
                    for (int b = 0; b < 2; b++)
#pragma unroll
                        for (int q = 0; q < 4; q++) c2[a][b][q] = 0.f;
            } else {
#pragma unroll
                for (int j = 0; j < 4; j++) {
                    float4 v = ((float4*)c2s)[j];
                    c2[j >> 1][j & 1][0] = v.x; c2[j >> 1][j & 1][1] = v.y;
                    c2[j >> 1][j & 1][2] = v.z; c2[j >> 1][j & 1][3] = v.w;
                }
            }
            const uint32_t aB = sbase + SO_H1
                              + ((mbase + (lane & 15)) * 264 + (lane >> 4) * 8) * 2;
#pragma unroll
            for (int ks = 0; ks < 16; ks++) {
                uint32_t a0[4], a1[4];
                LDM4(a0, aB + ks * 32);
                LDM4(a1, aB + 8448 + ks * 32);   /* mt=1: 16*264*2 */
#pragma unroll
                for (int nt = 0; nt < 2; nt++) {
                    int n  = wn * 16 + nt * 8 + gid;
                    int kk = nb * 256 + ks * 16 + tIG * 2;
                    uint32_t bb0 = *(const uint32_t*)(g_W2T + n * H1_N + kk);
                    uint32_t bb1 = *(const uint32_t*)(g_W2T + n * H1_N + kk + 8);
                    MMA(c2[0][nt], a0, bb0, bb1);
                    MMA(c2[1][nt], a1, bb0, bb1);
                }
            }
            if (nb == 0) {
#pragma unroll
                for (int j = 0; j < 4; j++) {
                    float4 v;
                    v.x = c2[j >> 1][j & 1][0]; v.y = c2[j >> 1][j & 1][1];
                    v.z = c2[j >> 1][j & 1][2]; v.w = c2[j >> 1][j & 1][3];
                    ((float4*)c2s)[j] = v;
                }
            } else {
                /* ---- h2 = relu(c2 + b2) -> fp32 [128][66] (overlay) ---- */
                __syncthreads();
                float* h2s = (float*)(smem + SO_H1);
#pragma unroll
                for (int mt = 0; mt < 2; mt++)
#pragma unroll
                for (int nt = 0; nt < 2; nt++) {
                    int m0 = mbase + mt * 16 + gid;
                    int n  = wn * 16 + nt * 8 + tIG * 2;
                    h2s[m0 * 66 + n]           = fmaxf(c2[mt][nt][0] + b2s[n],     0.f);
                    h2s[m0 * 66 + n + 1]       = fmaxf(c2[mt][nt][1] + b2s[n + 1], 0.f);
                    h2s[(m0 + 8) * 66 + n]     = fmaxf(c2[mt][nt][2] + b2s[n],     0.f);
                    h2s[(m0 + 8) * 66 + n + 1] = fmaxf(c2[mt][nt][3] + b2s[n + 1], 0.f);
                }
            }
        }
        __syncthreads();
    }

    /* ---- layer3 + softmax ---- */
    float* h2s = (float*)(smem + SO_H1);
    if (tid < 128) {
        float l0 = b3s[0], l1 = b3s[1];
#pragma unroll
        for (int k = 0; k < 64; k++) {
            float h = h2s[tid * 66 + k];
            l0 = fmaf(h, w3s[2 * k],     l0);
            l1 = fmaf(h, w3s[2 * k + 1], l1);
        }
        if (tid < rows) {
            float mx = fmaxf(l0, l1);
            float e0 = __expf(l0 - mx), e1 = __expf(l1 - mx);
            float inv = 1.f / (e0 + e1);
            out[ridx[tid] * 2 + 0] = e0 * inv;
            out[ridx[tid] * 2 + 1] = e1 * inv;
        }
    }
}

/* ---------------- launch: 4 kernels, fused_mma in profiled slot #4 ---------------- */
extern "C" void kernel_launch(void* const* d_in, const int* in_sizes, int n_in,
                              void* d_out, int out_size)
{
    const float* x  = (const float*)d_in[0];
    const int*   y  = (const int*)  d_in[1];
    const float* W1 = (const float*)d_in[2];
    const float* b1 = (const float*)d_in[3];
    const float* W2 = (const float*)d_in[4];
    const float* b2 = (const float*)d_in[5];
    const float* W3 = (const float*)d_in[6];
    const float* b3 = (const float*)d_in[7];
    float* out = (float*)d_out;

    cudaFuncSetAttribute(fused_mma, cudaFuncAttributeMaxDynamicSharedMemorySize, SMEM_TOT);

    bake_all<<<dim3(32, 8, E_N + 1), 256>>>(W1, W2);   /* 1 */
    route_hist_tiles<<<32, 256>>>(y);                   /* 2 */
    route_scatter<<<B_N / 256, 256>>>(y);               /* 3 */
    fused_mma<<<MAX_TILES, NTHREADS, SMEM_TOT>>>(x, b1, b2, W3, b3, out);  /* 4 */
}

// round 16
// speedup vs baseline: 1.2461x; 1.2461x over previous
#include <cuda_runtime.h>
#include <cuda_fp16.h>
#include <stdint.h>
#include <math.h>

#define B_N  16384
#define D_N  2048
#define E_N  10
#define H1_N 512
#define H2_N 64
#define TMS  128
#define KC   64
#define NCHUNKS (D_N / KC)          /* 32 */
#define MAX_TILES (B_N / TMS + E_N) /* 138 */
#define NTHREADS 512

/* ---- smem byte offsets ---- */
#define SO_RIDX 0          /* 128 int */
#define SO_B1   512        /* 512 f   */
#define SO_B2   2560       /* 64 f    */
#define SO_W3   2816       /* 128 f   */
#define SO_B3   3328       /* 2 f     */
#define SO_A    4096       /* 2 x 18432 (A tiles [128][72] fp16) -> ends 40960 */
#define SO_BB   40960      /* 2 x 36864 (B tiles [256][72] fp16) -> ends 114688 */
#define SO_H1   4096       /* OVERLAY: h1 [128][264] fp16 = 67584 (bufs dead)  */
#define SMEM_TOT 114688    /* 1 CTA/SM, 512 threads, 16 warps */

/* ---------------- device globals ---------------- */
__device__ __align__(16) __half g_W1T[(size_t)E_N * H1_N * D_N]; /* [e][n(512)][k(2048)] */
__device__ __align__(16) __half g_W2T[H2_N * H1_N];              /* [n(64)][k(512)]      */
__device__ int g_cnt[E_N];          /* zero-init; reset by route kernel each run */
__device__ int g_done;              /* zero-init; reset by route kernel each run */
__device__ volatile int g_ready;    /* zero-init; reset by route kernel each run */
__device__ int g_cur[E_N];
__device__ int g_sorted[B_N];
__device__ int g_te[MAX_TILES], g_ts[MAX_TILES], g_tr[MAX_TILES];
__device__ int g_ntile;

/* ---------------- helpers ---------------- */
__device__ __forceinline__ uint32_t smem_u32(const void* p) {
    uint32_t a;
    asm("{ .reg .u64 t; cvta.to.shared.u64 t, %1; cvt.u32.u64 %0, t; }" : "=r"(a) : "l"(p));
    return a;
}

#define LDM4(r, addr) asm volatile( \
    "ldmatrix.sync.aligned.m8n8.x4.shared.b16 {%0,%1,%2,%3}, [%4];" \
    : "=r"((r)[0]), "=r"((r)[1]), "=r"((r)[2]), "=r"((r)[3]) : "r"(addr))

#define MMA(c, a, b0, b1) asm volatile( \
    "mma.sync.aligned.m16n8k16.row.col.f32.f16.f16.f32 " \
    "{%0,%1,%2,%3},{%4,%5,%6,%7},{%8,%9},{%0,%1,%2,%3};" \
    : "+f"((c)[0]), "+f"((c)[1]), "+f"((c)[2]), "+f"((c)[3]) \
    : "r"((a)[0]), "r"((a)[1]), "r"((a)[2]), "r"((a)[3]), "r"(b0), "r"(b1))

#define CP_ASYNC16(dst, src) asm volatile( \
    "cp.async.cg.shared.global [%0], [%1], 16;" :: "r"(dst), "l"(src))
#define CP_COMMIT() asm volatile("cp.async.commit_group;" ::: "memory")
#define CP_WAIT0()  asm volatile("cp.async.wait_group 0;" ::: "memory")

/* ------- bake W1 + W2 in one kernel (z==E_N branch does W2) ------- */
__global__ void bake_all(const float* __restrict__ W1, const float* __restrict__ W2) {
    __shared__ float t[64][65];
    const int tid = threadIdx.x;
    if (blockIdx.z == E_N) {
        if (blockIdx.x >= 16 || blockIdx.y >= 2) return;
        const int kb = blockIdx.x, nbb = blockIdx.y;
#pragma unroll
        for (int i = 0; i < 4; i++) {
            int idx = tid + i * 256, r = idx >> 5, c = idx & 31;
            t[r][c] = W2[(kb * 32 + r) * H2_N + nbb * 32 + c];
        }
        __syncthreads();
#pragma unroll
        for (int i = 0; i < 4; i++) {
            int idx = tid + i * 256, n = idx >> 5, k = idx & 31;
            g_W2T[(nbb * 32 + n) * H1_N + kb * 32 + k] = __float2half_rn(t[k][n]);
        }
        return;
    }
    const int kb = blockIdx.x, hb = blockIdx.y, e = blockIdx.z;
    const float* src = W1 + ((size_t)e * D_N + kb * 64) * H1_N + hb * 64;
#pragma unroll
    for (int i = 0; i < 4; i++) {
        int idx = tid + i * 256;
        int r = idx >> 4, c4 = idx & 15;
        float4 v = *(const float4*)(src + (size_t)r * H1_N + c4 * 4);
        t[r][c4 * 4 + 0] = v.x; t[r][c4 * 4 + 1] = v.y;
        t[r][c4 * 4 + 2] = v.z; t[r][c4 * 4 + 3] = v.w;
    }
    __syncthreads();
#pragma unroll
    for (int i = 0; i < 2; i++) {
        int idx = tid + i * 256;
        int n = idx >> 3, kg = idx & 7, k0 = kg * 8;
        __half2 p[4];
#pragma unroll
        for (int j = 0; j < 4; j++)
            p[j] = __floats2half2_rn(t[k0 + 2 * j][n], t[k0 + 2 * j + 1][n]);
        uint4 u;
        u.x = *(uint32_t*)&p[0]; u.y = *(uint32_t*)&p[1];
        u.z = *(uint32_t*)&p[2]; u.w = *(uint32_t*)&p[3];
        *(uint4*)(g_W1T + ((size_t)e * H1_N + hb * 64 + n) * D_N + kb * 64 + k0) = u;
    }
}

/* ------- ALL routing in ONE kernel: 64 co-resident blocks.
   Phase 1: per-block hist -> global.  Last-done block builds tile table,
   publishes g_ready.  Phase 2: all blocks spin on g_ready, then scatter. ------- */
__global__ void route_all(const int* __restrict__ y) {
    __shared__ int lcnt[E_N], lbase[E_N], lcur[E_N];
    const int t = threadIdx.x, i0 = blockIdx.x * 256;
    if (t < E_N) { lcnt[t] = 0; lcur[t] = 0; }
    __syncthreads();
    const int e = y[i0 + t];
    atomicAdd(&lcnt[e], 1);
    __syncthreads();
    if (t < E_N && lcnt[t]) atomicAdd(&g_cnt[t], lcnt[t]);
    __threadfence();
    __shared__ int last;
    if (t == 0) last = (atomicAdd(&g_done, 1) == (int)gridDim.x - 1);
    __syncthreads();
    if (last && t < 32) {
        int cn = (t < E_N) ? g_cnt[t] : 0;
        if (t < E_N) g_cnt[t] = 0;
        if (t == 0) g_done = 0;
        int v = cn;
#pragma unroll
        for (int d = 1; d < 32; d <<= 1) {
            int u = __shfl_up_sync(0xFFFFFFFFu, v, d);
            if (t >= d) v += u;
        }
        int off = v - cn;
        int ntl = (cn + TMS - 1) / TMS;
        int tv = ntl;
#pragma unroll
        for (int d = 1; d < 32; d <<= 1) {
            int u = __shfl_up_sync(0xFFFFFFFFu, tv, d);
            if (t >= d) tv += u;
        }
        int tbase = tv - ntl;
        if (t < E_N) {
            g_cur[t] = off;
            for (int s = 0, j = 0; s < cn; s += TMS, j++) {
                g_te[tbase + j] = t;
                g_ts[tbase + j] = off + s;
                g_tr[tbase + j] = (cn - s) < TMS ? (cn - s) : TMS;
            }
        }
        if (t == 31) g_ntile = tv;
        __threadfence();
        if (t == 0) g_ready = 1;
    }
    /* phase 2: wait for table (all 64 blocks co-resident -> spin is safe) */
    if (t == 0) {
        while (g_ready == 0) __nanosleep(64);
    }
    __syncthreads();
    if (t < E_N && lcnt[t]) lbase[t] = atomicAdd(&g_cur[t], lcnt[t]);
    __syncthreads();
    int off = atomicAdd(&lcur[e], 1);
    g_sorted[lbase[e] + off] = i0 + t;
    /* reset g_ready for next replay: last block to finish scatter clears it */
    __threadfence();
    if (t == 0 && atomicAdd(&g_done, 1) == (int)gridDim.x - 1) {
        g_done = 0;
        g_ready = 0;
    }
}

/* ------- fused mma.sync kernel: M=128 tile, 512 threads, 16 warps, 1 CTA/SM ------- */
__global__ void __launch_bounds__(NTHREADS, 1)
fused_mma(const float* __restrict__ x, const float* __restrict__ b1,
          const float* __restrict__ b2, const float* __restrict__ W3,
          const float* __restrict__ b3, float* __restrict__ out)
{
    const int bid = blockIdx.x;
    if (bid >= g_ntile) return;
    extern __shared__ char smem[];
    const uint32_t sbase = smem_u32(smem);
    const int tid = threadIdx.x, lane = tid & 31, wid = tid >> 5;
    const int gid = lane >> 2, tIG = lane & 3;
    const int wm = wid >> 2, wn = wid & 3;      /* 4M x 4N warp grid */
    const int mbase = wm * 32;
    const int e = g_te[bid], st = g_ts[bid], rows = g_tr[bid];

    int*   ridx = (int*)(smem + SO_RIDX);
    float* b1s  = (float*)(smem + SO_B1);
    float* b2s  = (float*)(smem + SO_B2);
    float* w3s  = (float*)(smem + SO_W3);
    float* b3s  = (float*)(smem + SO_B3);
    if (tid < 128) {
        int r = tid < rows ? tid : (rows - 1);
        ridx[tid] = g_sorted[st + r];
        ((float4*)b1s)[tid] = ((const float4*)(b1 + e * H1_N))[tid];
    }
    if (tid < 16) ((float4*)b2s)[tid] = ((const float4*)b2)[tid];
    if (tid < 32) ((float4*)w3s)[tid] = ((const float4*)W3)[tid];
    if (tid < 2)  b3s[tid] = b3[tid];
    __syncthreads();

    const __half* W1Te = g_W1T + (size_t)e * H1_N * D_N;

    float c2[2][2][4];
#pragma unroll
    for (int a = 0; a < 2; a++)
#pragma unroll
        for (int b = 0; b < 2; b++)
#pragma unroll
            for (int q = 0; q < 4; q++) c2[a][b][q] = 0.f;

    for (int nb = 0; nb < 2; nb++) {
        float c1[2][8][4];
#pragma unroll
        for (int a = 0; a < 2; a++)
#pragma unroll
            for (int b = 0; b < 8; b++)
#pragma unroll
                for (int q = 0; q < 4; q++) c1[a][b][q] = 0.f;

        /* ---- prologue: chunk 0 -> buf 0 ---- */
#pragma unroll
        for (int i = 0; i < 4; i++) {
            int idx = tid + i * NTHREADS, row = idx >> 3, seg = idx & 7;
            uint32_t dst = sbase + SO_BB + (row * 72 + seg * 8) * 2;
            CP_ASYNC16(dst, W1Te + (size_t)(nb * 256 + row) * D_N + seg * 8);
        }
#pragma unroll
        for (int i = 0; i < 4; i++) {
            int idx = tid + i * NTHREADS, row = idx >> 4, f4 = idx & 15;
            float4 v = *((const float4*)(x + (size_t)ridx[row] * D_N) + f4);
            __half2 h0 = __floats2half2_rn(v.x, v.y);
            __half2 h1h = __floats2half2_rn(v.z, v.w);
            uint2 u; u.x = *(uint32_t*)&h0; u.y = *(uint32_t*)&h1h;
            *(uint2*)(smem + SO_A + (row * 72 + f4 * 4) * 2) = u;
        }
        CP_COMMIT();

        /* ---- mainloop ---- */
        for (int c = 0; c < NCHUNKS; c++) {
            const int buf = c & 1, nbuf = buf ^ 1;
            CP_WAIT0();
            __syncthreads();

            /* prefetch next: B via cp.async; A as RAW float4 held across MMA */
            float4 av[4];
            if (c + 1 < NCHUNKS) {
#pragma unroll
                for (int i = 0; i < 4; i++) {
                    int idx = tid + i * NTHREADS, row = idx >> 3, seg = idx & 7;
                    uint32_t dst = sbase + SO_BB + nbuf * 36864 + (row * 72 + seg * 8) * 2;
                    CP_ASYNC16(dst, W1Te + (size_t)(nb * 256 + row) * D_N + (c + 1) * KC + seg * 8);
                }
#pragma unroll
                for (int i = 0; i < 4; i++) {
                    int idx = tid + i * NTHREADS, row = idx >> 4, f4 = idx & 15;
                    av[i] = *((const float4*)(x + (size_t)ridx[row] * D_N + (c + 1) * KC) + f4);
                }
            }

            const uint32_t aB = sbase + SO_A + buf * 18432
                              + ((mbase + (lane & 15)) * 72 + (lane >> 4) * 8) * 2;
            const uint32_t bB = sbase + SO_BB + buf * 36864
                              + ((wn * 64 + (lane & 7) + ((lane >> 4) & 1) * 8) * 72
                                 + ((lane >> 3) & 1) * 8) * 2;
#pragma unroll
            for (int ks = 0; ks < 4; ks++) {
                uint32_t a0[4], a1[4];
                LDM4(a0, aB + ks * 32);
                LDM4(a1, aB + 2304 + ks * 32);   /* mt=1: 16*72*2 */
#pragma unroll
                for (int nt2 = 0; nt2 < 4; nt2++) {
                    uint32_t bb[4];
                    LDM4(bb, bB + nt2 * 2304 + ks * 32);
                    MMA(c1[0][nt2 * 2],     a0, bb[0], bb[1]);
                    MMA(c1[0][nt2 * 2 + 1], a0, bb[2], bb[3]);
                    MMA(c1[1][nt2 * 2],     a1, bb[0], bb[1]);
                    MMA(c1[1][nt2 * 2 + 1], a1, bb[2], bb[3]);
                }
            }

            if (c + 1 < NCHUNKS) {
#pragma unroll
                for (int i = 0; i < 4; i++) {
                    int idx = tid + i * NTHREADS, row = idx >> 4, f4 = idx & 15;
                    __half2 h0 = __floats2half2_rn(av[i].x, av[i].y);
                    __half2 h1h = __floats2half2_rn(av[i].z, av[i].w);
                    uint2 u; u.x = *(uint32_t*)&h0; u.y = *(uint32_t*)&h1h;
                    *(uint2*)(smem + SO_A + nbuf * 18432 + (row * 72 + f4 * 4) * 2) = u;
                }
                CP_COMMIT();
            }
        }
        __syncthreads();   /* overlay safety */

        /* ---- h1 = relu(c1 + b1) -> fp16 stage [128][264] (overlay) ---- */
        __half* h1s = (__half*)(smem + SO_H1);
#pragma unroll
        for (int mt = 0; mt < 2; mt++)
#pragma unroll
        for (int nt = 0; nt < 8; nt++) {
            int m0 = mbase + mt * 16 + gid;
            int cl = wn * 64 + nt * 8 + tIG * 2;
            int cg = nb * 256 + cl;
            __half2 lo = __floats2half2_rn(fmaxf(c1[mt][nt][0] + b1s[cg],     0.f),
                                           fmaxf(c1[mt][nt][1] + b1s[cg + 1], 0.f));
            __half2 hi = __floats2half2_rn(fmaxf(c1[mt][nt][2] + b1s[cg],     0.f),
                                           fmaxf(c1[mt][nt][3] + b1s[cg + 1], 0.f));
            *(__half2*)(h1s + m0 * 264 + cl)       = lo;
            *(__half2*)(h1s + (m0 + 8) * 264 + cl) = hi;
        }
        __syncthreads();

        /* ---- layer2 partial GEMM (K = this pass's 256 cols); W2 from L2 ---- */
        {
            const uint32_t aB = sbase + SO_H1
                              + ((mbase + (lane & 15)) * 264 + (lane >> 4) * 8) * 2;
#pragma unroll
            for (int ks = 0; ks < 16; ks++) {
                uint32_t a0[4], a1[4];
                LDM4(a0, aB + ks * 32);
                LDM4(a1, aB + 8448 + ks * 32);   /* mt=1: 16*264*2 */
#pragma unroll
                for (int nt = 0; nt < 2; nt++) {
                    int n  = wn * 16 + nt * 8 + gid;
                    int kk = nb * 256 + ks * 16 + tIG * 2;
                    uint32_t bb0 = *(const uint32_t*)(g_W2T + n * H1_N + kk);
                    uint32_t bb1 = *(const uint32_t*)(g_W2T + n * H1_N + kk + 8);
                    MMA(c2[0][nt], a0, bb0, bb1);
                    MMA(c2[1][nt], a1, bb0, bb1);
                }
            }
        }
        __syncthreads();
    }

    /* ---- h2 = relu(c2 + b2) -> fp32 [128][66] (overlay) ---- */
    float* h2s = (float*)(smem + SO_H1);
#pragma unroll
    for (int mt = 0; mt < 2; mt++)
#pragma unroll
    for (int nt = 0; nt < 2; nt++) {
        int m0 = mbase + mt * 16 + gid;
        int n  = wn * 16 + nt * 8 + tIG * 2;
        h2s[m0 * 66 + n]           = fmaxf(c2[mt][nt][0] + b2s[n],     0.f);
        h2s[m0 * 66 + n + 1]       = fmaxf(c2[mt][nt][1] + b2s[n + 1], 0.f);
        h2s[(m0 + 8) * 66 + n]     = fmaxf(c2[mt][nt][2] + b2s[n],     0.f);
        h2s[(m0 + 8) * 66 + n + 1] = fmaxf(c2[mt][nt][3] + b2s[n + 1], 0.f);
    }
    __syncthreads();

    /* ---- layer3 + softmax ---- */
    if (tid < 128) {
        float l0 = b3s[0], l1 = b3s[1];
#pragma unroll
        for (int k = 0; k < 64; k++) {
            float h = h2s[tid * 66 + k];
            l0 = fmaf(h, w3s[2 * k],     l0);
            l1 = fmaf(h, w3s[2 * k + 1], l1);
        }
        if (tid < rows) {
            float mx = fmaxf(l0, l1);
            float e0 = __expf(l0 - mx), e1 = __expf(l1 - mx);
            float inv = 1.f / (e0 + e1);
            out[ridx[tid] * 2 + 0] = e0 * inv;
            out[ridx[tid] * 2 + 1] = e1 * inv;
        }
    }
}

/* ---------------- launch: 3 kernels ---------------- */
extern "C" void kernel_launch(void* const* d_in, const int* in_sizes, int n_in,
                              void* d_out, int out_size)
{
    const float* x  = (const float*)d_in[0];
    const int*   y  = (const int*)  d_in[1];
    const float* W1 = (const float*)d_in[2];
    const float* b1 = (const float*)d_in[3];
    const float* W2 = (const float*)d_in[4];
    const float* b2 = (const float*)d_in[5];
    const float* W3 = (const float*)d_in[6];
    const float* b3 = (const float*)d_in[7];
    float* out = (float*)d_out;

    cudaFuncSetAttribute(fused_mma, cudaFuncAttributeMaxDynamicSharedMemorySize, SMEM_TOT);

    bake_all<<<dim3(32, 8, E_N + 1), 256>>>(W1, W2);   /* 1 */
    route_all<<<B_N / 256, 256>>>(y);                   /* 2 */
    fused_mma<<<MAX_TILES, NTHREADS, SMEM_TOT>>>(x, b1, b2, W3, b3, out);  /* 3 */
}

// round 17
// speedup vs baseline: 1.2789x; 1.0263x over previous
#include <cuda_runtime.h>
#include <cuda_fp16.h>
#include <stdint.h>
#include <math.h>

#define B_N  16384
#define D_N  2048
#define E_N  10
#define H1_N 512
#define H2_N 64
#define TMS  128
#define KC   64
#define NCHUNKS (D_N / KC)          /* 32 */
#define MAX_TILES (B_N / TMS + E_N) /* 138 */
#define NTHREADS 512

/* prep_all block ranges */
#define ROUTE_BLOCKS (B_N / 256)          /* 64  */
#define BAKE_W1_BLOCKS (32 * 8 * E_N)     /* 2560 */
#define BAKE_W2_BLOCKS 32
#define PREP_BLOCKS (ROUTE_BLOCKS + BAKE_W1_BLOCKS + BAKE_W2_BLOCKS)  /* 2656 */

/* ---- smem byte offsets (fused) ---- */
#define SO_RIDX 0          /* 128 int */
#define SO_B1   512        /* 512 f   */
#define SO_B2   2560       /* 64 f    */
#define SO_W3   2816       /* 128 f   */
#define SO_B3   3328       /* 2 f     */
#define SO_A    4096       /* 2 x 18432 (A tiles [128][72] fp16) -> ends 40960 */
#define SO_BB   40960      /* 2 x 36864 (B tiles [256][72] fp16) -> ends 114688 */
#define SO_H1   4096       /* OVERLAY: h1 [128][264] fp16 = 67584 (bufs dead)  */
#define SMEM_TOT 114688    /* 1 CTA/SM, 512 threads, 16 warps */

/* ---------------- device globals ---------------- */
__device__ __align__(16) __half g_W1T[(size_t)E_N * H1_N * D_N]; /* [e][n(512)][k(2048)] */
__device__ __align__(16) __half g_W2T[H2_N * H1_N];              /* [n(64)][k(512)]      */
__device__ int g_cnt[E_N];          /* zero-init; reset each run */
__device__ int g_done;              /* zero-init; reset each run */
__device__ volatile int g_ready;    /* zero-init; reset each run */
__device__ int g_cur[E_N];
__device__ int g_sorted[B_N];
__device__ int g_te[MAX_TILES], g_ts[MAX_TILES], g_tr[MAX_TILES];
__device__ int g_ntile;

/* ---------------- helpers ---------------- */
__device__ __forceinline__ uint32_t smem_u32(const void* p) {
    uint32_t a;
    asm("{ .reg .u64 t; cvta.to.shared.u64 t, %1; cvt.u32.u64 %0, t; }" : "=r"(a) : "l"(p));
    return a;
}

#define LDM4(r, addr) asm volatile( \
    "ldmatrix.sync.aligned.m8n8.x4.shared.b16 {%0,%1,%2,%3}, [%4];" \
    : "=r"((r)[0]), "=r"((r)[1]), "=r"((r)[2]), "=r"((r)[3]) : "r"(addr))

#define MMA(c, a, b0, b1) asm volatile( \
    "mma.sync.aligned.m16n8k16.row.col.f32.f16.f16.f32 " \
    "{%0,%1,%2,%3},{%4,%5,%6,%7},{%8,%9},{%0,%1,%2,%3};" \
    : "+f"((c)[0]), "+f"((c)[1]), "+f"((c)[2]), "+f"((c)[3]) \
    : "r"((a)[0]), "r"((a)[1]), "r"((a)[2]), "r"((a)[3]), "r"(b0), "r"(b1))

#define CP_ASYNC16(dst, src) asm volatile( \
    "cp.async.cg.shared.global [%0], [%1], 16;" :: "r"(dst), "l"(src))
#define CP_COMMIT() asm volatile("cp.async.commit_group;" ::: "memory")
#define CP_WAIT0()  asm volatile("cp.async.wait_group 0;" ::: "memory")

/* ------- prep_all: routing (blocks 0..63) + bake W1/W2 (blocks 64..) -------
   Route and bake are data-independent; merging them in one launch lets the
   ~5us routing hide entirely under the ~13us bake memory phase. Route blocks
   come FIRST so they are scheduled immediately and co-resident (spin-safe);
   bake blocks always terminate, so the scheduler makes progress. ------- */
__global__ void prep_all(const int* __restrict__ y,
                         const float* __restrict__ W1,
                         const float* __restrict__ W2) {
    const int tid = threadIdx.x;

    if (blockIdx.x < ROUTE_BLOCKS) {
        /* ---------------- routing ---------------- */
        __shared__ int lcnt[E_N], lbase[E_N], lcur[E_N];
        const int i0 = blockIdx.x * 256;
        if (tid < E_N) { lcnt[tid] = 0; lcur[tid] = 0; }
        __syncthreads();
        const int e = y[i0 + tid];
        atomicAdd(&lcnt[e], 1);
        __syncthreads();
        if (tid < E_N && lcnt[tid]) atomicAdd(&g_cnt[tid], lcnt[tid]);
        __threadfence();
        __shared__ int last;
        if (tid == 0) last = (atomicAdd(&g_done, 1) == ROUTE_BLOCKS - 1);
        __syncthreads();
        if (last && tid < 32) {
            int cn = (tid < E_N) ? g_cnt[tid] : 0;
            if (tid < E_N) g_cnt[tid] = 0;
            if (tid == 0) g_done = 0;
            int v = cn;
#pragma unroll
            for (int d = 1; d < 32; d <<= 1) {
                int u = __shfl_up_sync(0xFFFFFFFFu, v, d);
                if (tid >= d) v += u;
            }
            int off = v - cn;
            int ntl = (cn + TMS - 1) / TMS;
            int tv = ntl;
#pragma unroll
            for (int d = 1; d < 32; d <<= 1) {
                int u = __shfl_up_sync(0xFFFFFFFFu, tv, d);
                if (tid >= d) tv += u;
            }
            int tbase = tv - ntl;
            if (tid < E_N) {
                g_cur[tid] = off;
                for (int s = 0, j = 0; s < cn; s += TMS, j++) {
                    g_te[tbase + j] = tid;
                    g_ts[tbase + j] = off + s;
                    g_tr[tbase + j] = (cn - s) < TMS ? (cn - s) : TMS;
                }
            }
            if (tid == 31) g_ntile = tv;
            __threadfence();
            if (tid == 0) g_ready = 1;
        }
        if (tid == 0) {
            while (g_ready == 0) __nanosleep(64);
        }
        __syncthreads();
        if (tid < E_N && lcnt[tid]) lbase[tid] = atomicAdd(&g_cur[tid], lcnt[tid]);
        __syncthreads();
        int off = atomicAdd(&lcur[e], 1);
        g_sorted[lbase[e] + off] = i0 + tid;
        __threadfence();
        if (tid == 0 && atomicAdd(&g_done, 1) == ROUTE_BLOCKS - 1) {
            g_done = 0;
            g_ready = 0;
        }
        return;
    }

    /* ---------------- bake ---------------- */
    __shared__ float t[64][65];
    const int i = blockIdx.x - ROUTE_BLOCKS;
    if (i >= BAKE_W1_BLOCKS) {
        /* W2 transpose: 32 blocks of 32x32 tiles */
        const int j = i - BAKE_W1_BLOCKS;
        const int kb = j & 15, nbb = j >> 4;
#pragma unroll
        for (int q = 0; q < 4; q++) {
            int idx = tid + q * 256, r = idx >> 5, c = idx & 31;
            t[r][c] = W2[(kb * 32 + r) * H2_N + nbb * 32 + c];
        }
        __syncthreads();
#pragma unroll
        for (int q = 0; q < 4; q++) {
            int idx = tid + q * 256, n = idx >> 5, k = idx & 31;
            g_W2T[(nbb * 32 + n) * H1_N + kb * 32 + k] = __float2half_rn(t[k][n]);
        }
        return;
    }
    const int e  = i >> 8;           /* / 256 */
    const int rm = i & 255;
    const int kb = rm & 31, hb = rm >> 5;
    const float* src = W1 + ((size_t)e * D_N + kb * 64) * H1_N + hb * 64;
#pragma unroll
    for (int q = 0; q < 4; q++) {
        int idx = tid + q * 256;
        int r = idx >> 4, c4 = idx & 15;
        float4 v = *(const float4*)(src + (size_t)r * H1_N + c4 * 4);
        t[r][c4 * 4 + 0] = v.x; t[r][c4 * 4 + 1] = v.y;
        t[r][c4 * 4 + 2] = v.z; t[r][c4 * 4 + 3] = v.w;
    }
    __syncthreads();
#pragma unroll
    for (int q = 0; q < 2; q++) {
        int idx = tid + q * 256;
        int n = idx >> 3, kg = idx & 7, k0 = kg * 8;
        __half2 p[4];
#pragma unroll
        for (int j = 0; j < 4; j++)
            p[j] = __floats2half2_rn(t[k0 + 2 * j][n], t[k0 + 2 * j + 1][n]);
        uint4 u;
        u.x = *(uint32_t*)&p[0]; u.y = *(uint32_t*)&p[1];
        u.z = *(uint32_t*)&p[2]; u.w = *(uint32_t*)&p[3];
        *(uint4*)(g_W1T + ((size_t)e * H1_N + hb * 64 + n) * D_N + kb * 64 + k0) = u;
    }
}

/* ------- fused mma.sync kernel: M=128 tile, 512 threads, 16 warps, 1 CTA/SM ------- */
__global__ void __launch_bounds__(NTHREADS, 1)
fused_mma(const float* __restrict__ x, const float* __restrict__ b1,
          const float* __restrict__ b2, const float* __restrict__ W3,
          const float* __restrict__ b3, float* __restrict__ out)
{
    const int bid = blockIdx.x;
    if (bid >= g_ntile) return;
    extern __shared__ char smem[];
    const uint32_t sbase = smem_u32(smem);
    const int tid = threadIdx.x, lane = tid & 31, wid = tid >> 5;
    const int gid = lane >> 2, tIG = lane & 3;
    const int wm = wid >> 2, wn = wid & 3;      /* 4M x 4N warp grid */
    const int mbase = wm * 32;
    const int e = g_te[bid], st = g_ts[bid], rows = g_tr[bid];

    int*   ridx = (int*)(smem + SO_RIDX);
    float* b1s  = (float*)(smem + SO_B1);
    float* b2s  = (float*)(smem + SO_B2);
    float* w3s  = (float*)(smem + SO_W3);
    float* b3s  = (float*)(smem + SO_B3);
    if (tid < 128) {
        int r = tid < rows ? tid : (rows - 1);
        ridx[tid] = g_sorted[st + r];
        ((float4*)b1s)[tid] = ((const float4*)(b1 + e * H1_N))[tid];
    }
    if (tid < 16) ((float4*)b2s)[tid] = ((const float4*)b2)[tid];
    if (tid < 32) ((float4*)w3s)[tid] = ((const float4*)W3)[tid];
    if (tid < 2)  b3s[tid] = b3[tid];
    __syncthreads();

    const __half* W1Te = g_W1T + (size_t)e * H1_N * D_N;

    float c2[2][2][4];
#pragma unroll
    for (int a = 0; a < 2; a++)
#pragma unroll
        for (int b = 0; b < 2; b++)
#pragma unroll
            for (int q = 0; q < 4; q++) c2[a][b][q] = 0.f;

    for (int nb = 0; nb < 2; nb++) {
        float c1[2][8][4];
#pragma unroll
        for (int a = 0; a < 2; a++)
#pragma unroll
            for (int b = 0; b < 8; b++)
#pragma unroll
                for (int q = 0; q < 4; q++) c1[a][b][q] = 0.f;

        /* ---- prologue: chunk 0 -> buf 0 ---- */
#pragma unroll
        for (int i = 0; i < 4; i++) {
            int idx = tid + i * NTHREADS, row = idx >> 3, seg = idx & 7;
            uint32_t dst = sbase + SO_BB + (row * 72 + seg * 8) * 2;
            CP_ASYNC16(dst, W1Te + (size_t)(nb * 256 + row) * D_N + seg * 8);
        }
#pragma unroll
        for (int i = 0; i < 4; i++) {
            int idx = tid + i * NTHREADS, row = idx >> 4, f4 = idx & 15;
            float4 v = *((const float4*)(x + (size_t)ridx[row] * D_N) + f4);
            __half2 h0 = __floats2half2_rn(v.x, v.y);
            __half2 h1h = __floats2half2_rn(v.z, v.w);
            uint2 u; u.x = *(uint32_t*)&h0; u.y = *(uint32_t*)&h1h;
            *(uint2*)(smem + SO_A + (row * 72 + f4 * 4) * 2) = u;
        }
        CP_COMMIT();

        /* ---- mainloop ---- */
        for (int c = 0; c < NCHUNKS; c++) {
            const int buf = c & 1, nbuf = buf ^ 1;
            CP_WAIT0();
            __syncthreads();

            /* prefetch next: B via cp.async; A as RAW float4 held across MMA */
            float4 av[4];
            if (c + 1 < NCHUNKS) {
#pragma unroll
                for (int i = 0; i < 4; i++) {
                    int idx = tid + i * NTHREADS, row = idx >> 3, seg = idx & 7;
                    uint32_t dst = sbase + SO_BB + nbuf * 36864 + (row * 72 + seg * 8) * 2;
                    CP_ASYNC16(dst, W1Te + (size_t)(nb * 256 + row) * D_N + (c + 1) * KC + seg * 8);
                }
#pragma unroll
                for (int i = 0; i < 4; i++) {
                    int idx = tid + i * NTHREADS, row = idx >> 4, f4 = idx & 15;
                    av[i] = *((const float4*)(x + (size_t)ridx[row] * D_N + (c + 1) * KC) + f4);
                }
            }

            const uint32_t aB = sbase + SO_A + buf * 18432
                              + ((mbase + (lane & 15)) * 72 + (lane >> 4) * 8) * 2;
            const uint32_t bB = sbase + SO_BB + buf * 36864
                              + ((wn * 64 + (lane & 7) + ((lane >> 4) & 1) * 8) * 72
                                 + ((lane >> 3) & 1) * 8) * 2;
#pragma unroll
            for (int ks = 0; ks < 4; ks++) {
                uint32_t a0[4], a1[4];
                LDM4(a0, aB + ks * 32);
                LDM4(a1, aB + 2304 + ks * 32);   /* mt=1: 16*72*2 */
#pragma unroll
                for (int nt2 = 0; nt2 < 4; nt2++) {
                    uint32_t bb[4];
                    LDM4(bb, bB + nt2 * 2304 + ks * 32);
                    MMA(c1[0][nt2 * 2],     a0, bb[0], bb[1]);
                    MMA(c1[0][nt2 * 2 + 1], a0, bb[2], bb[3]);
                    MMA(c1[1][nt2 * 2],     a1, bb[0], bb[1]);
                    MMA(c1[1][nt2 * 2 + 1], a1, bb[2], bb[3]);
                }
            }

            if (c + 1 < NCHUNKS) {
#pragma unroll
                for (int i = 0; i < 4; i++) {
                    int idx = tid + i * NTHREADS, row = idx >> 4, f4 = idx & 15;
                    __half2 h0 = __floats2half2_rn(av[i].x, av[i].y);
                    __half2 h1h = __floats2half2_rn(av[i].z, av[i].w);
                    uint2 u; u.x = *(uint32_t*)&h0; u.y = *(uint32_t*)&h1h;
                    *(uint2*)(smem + SO_A + nbuf * 18432 + (row * 72 + f4 * 4) * 2) = u;
                }
                CP_COMMIT();
            }
        }
        __syncthreads();   /* overlay safety */

        /* ---- h1 = relu(c1 + b1) -> fp16 stage [128][264] (overlay) ---- */
        __half* h1s = (__half*)(smem + SO_H1);
#pragma unroll
        for (int mt = 0; mt < 2; mt++)
#pragma unroll
        for (int nt = 0; nt < 8; nt++) {
            int m0 = mbase + mt * 16 + gid;
            int cl = wn * 64 + nt * 8 + tIG * 2;
            int cg = nb * 256 + cl;
            __half2 lo = __floats2half2_rn(fmaxf(c1[mt][nt][0] + b1s[cg],     0.f),
                                           fmaxf(c1[mt][nt][1] + b1s[cg + 1], 0.f));
            __half2 hi = __floats2half2_rn(fmaxf(c1[mt][nt][2] + b1s[cg],     0.f),
                                           fmaxf(c1[mt][nt][3] + b1s[cg + 1], 0.f));
            *(__half2*)(h1s + m0 * 264 + cl)       = lo;
            *(__half2*)(h1s + (m0 + 8) * 264 + cl) = hi;
        }
        __syncthreads();

        /* ---- layer2 partial GEMM (K = this pass's 256 cols); W2 from L2 ---- */
        {
            const uint32_t aB = sbase + SO_H1
                              + ((mbase + (lane & 15)) * 264 + (lane >> 4) * 8) * 2;
#pragma unroll
            for (int ks = 0; ks < 16; ks++) {
                uint32_t a0[4], a1[4];
                LDM4(a0, aB + ks * 32);
                LDM4(a1, aB + 8448 + ks * 32);   /* mt=1: 16*264*2 */
#pragma unroll
                for (int nt = 0; nt < 2; nt++) {
                    int n  = wn * 16 + nt * 8 + gid;
                    int kk = nb * 256 + ks * 16 + tIG * 2;
                    uint32_t bb0 = *(const uint32_t*)(g_W2T + n * H1_N + kk);
                    uint32_t bb1 = *(const uint32_t*)(g_W2T + n * H1_N + kk + 8);
                    MMA(c2[0][nt], a0, bb0, bb1);
                    MMA(c2[1][nt], a1, bb0, bb1);
                }
            }
        }
        __syncthreads();
    }

    /* ---- h2 = relu(c2 + b2) -> fp32 [128][66] (overlay) ---- */
    float* h2s = (float*)(smem + SO_H1);
#pragma unroll
    for (int mt = 0; mt < 2; mt++)
#pragma unroll
    for (int nt = 0; nt < 2; nt++) {
        int m0 = mbase + mt * 16 + gid;
        int n  = wn * 16 + nt * 8 + tIG * 2;
        h2s[m0 * 66 + n]           = fmaxf(c2[mt][nt][0] + b2s[n],     0.f);
        h2s[m0 * 66 + n + 1]       = fmaxf(c2[mt][nt][1] + b2s[n + 1], 0.f);
        h2s[(m0 + 8) * 66 + n]     = fmaxf(c2[mt][nt][2] + b2s[n],     0.f);
        h2s[(m0 + 8) * 66 + n + 1] = fmaxf(c2[mt][nt][3] + b2s[n + 1], 0.f);
    }
    __syncthreads();

    /* ---- layer3 + softmax ---- */
    if (tid < 128) {
        float l0 = b3s[0], l1 = b3s[1];
#pragma unroll
        for (int k = 0; k < 64; k++) {
            float h = h2s[tid * 66 + k];
            l0 = fmaf(h, w3s[2 * k],     l0);
            l1 = fmaf(h, w3s[2 * k + 1], l1);
        }
        if (tid < rows) {
            float mx = fmaxf(l0, l1);
            float e0 = __expf(l0 - mx), e1 = __expf(l1 - mx);
            float inv = 1.f / (e0 + e1);
            out[ridx[tid] * 2 + 0] = e0 * inv;
            out[ridx[tid] * 2 + 1] = e1 * inv;
        }
    }
}

/* ---------------- launch: 2 kernels ---------------- */
extern "C" void kernel_launch(void* const* d_in, const int* in_sizes, int n_in,
                              void* d_out, int out_size)
{
    const float* x  = (const float*)d_in[0];
    const int*   y  = (const int*)  d_in[1];
    const float* W1 = (const float*)d_in[2];
    const float* b1 = (const float*)d_in[3];
    const float* W2 = (const float*)d_in[4];
    const float* b2 = (const float*)d_in[5];
    const float* W3 = (const float*)d_in[6];
    const float* b3 = (const float*)d_in[7];
    float* out = (float*)d_out;

    cudaFuncSetAttribute(fused_mma, cudaFuncAttributeMaxDynamicSharedMemorySize, SMEM_TOT);

    prep_all<<<PREP_BLOCKS, 256>>>(y, W1, W2);                          /* 1 */
    fused_mma<<<MAX_TILES, NTHREADS, SMEM_TOT>>>(x, b1, b2, W3, b3, out); /* 2 */
}